// round 3
// baseline (speedup 1.0000x reference)
#include <cuda_runtime.h>
#include <cstring>

#define BB   8
#define CIN  8
#define COUT 16
#define HH   256
#define WW   256
#define HW   (HH * WW)          // 65536
#define NPIX (BB * HW)          // 524288
#define GROUPS_PER_IMG (HW / 4) // 16384 float4 pixel-groups per image

__device__ __forceinline__ float ex2(float v) {
    float r;
    asm("ex2.approx.ftz.f32 %0, %1;" : "=f"(r) : "f"(v));
    return r;
}

// Packed f32x2 ops (Blackwell sm_103a)
__device__ __forceinline__ float2 add2(float2 a, float2 b) {
    unsigned long long ra, rb, rr;
    memcpy(&ra, &a, 8); memcpy(&rb, &b, 8);
    asm("add.rn.f32x2 %0, %1, %2;" : "=l"(rr) : "l"(ra), "l"(rb));
    float2 r; memcpy(&r, &rr, 8);
    return r;
}
__device__ __forceinline__ float2 mul2(float2 a, float2 b) {
    unsigned long long ra, rb, rr;
    memcpy(&ra, &a, 8); memcpy(&rb, &b, 8);
    asm("mul.rn.f32x2 %0, %1, %2;" : "=l"(rr) : "l"(ra), "l"(rb));
    float2 r; memcpy(&r, &rr, 8);
    return r;
}
__device__ __forceinline__ float2 fma2(float2 a, float2 b, float2 c) {
    unsigned long long ra, rb, rc, rr;
    memcpy(&ra, &a, 8); memcpy(&rb, &b, 8); memcpy(&rc, &c, 8);
    asm("fma.rn.f32x2 %0, %1, %2, %3;" : "=l"(rr) : "l"(ra), "l"(rb), "l"(rc));
    float2 r; memcpy(&r, &rr, 8);
    return r;
}

// FMA-pipe exp2 for a packed pair (no MUFU). Valid for any g (clamped at -126).
// 2^f Taylor deg-5 on f in [-0.5,0.5], rel err ~2e-6.
struct PolyC {
    float2 MAGIC, NEG1, ONE, C1, C2, C3, C4, C5;
};
__device__ __forceinline__ float2 exp2_fma(float2 g, const PolyC& K) {
    float2 gc = make_float2(fmaxf(g.x, -126.0f), fmaxf(g.y, -126.0f)); // alu FMNMX x2
    float2 t  = add2(gc, K.MAGIC);          // round-to-nearest int in low bits
    float2 tm = fma2(K.MAGIC, K.NEG1, t);   // t - MAGIC = rint(gc)
    float2 f  = fma2(tm, K.NEG1, gc);       // gc - rint(gc) in [-0.5, 0.5]
    float2 p  = fma2(f, K.C5, K.C4);
    p = fma2(p, f, K.C3);
    p = fma2(p, f, K.C2);
    p = fma2(p, f, K.C1);
    p = fma2(p, f, K.ONE);
    // scale by 2^i via exponent-field add; magic's contribution to (bits<<23) is 0
    unsigned sx = __float_as_uint(t.x) << 23;
    unsigned sy = __float_as_uint(t.y) << 23;
    return make_float2(__uint_as_float(__float_as_uint(p.x) + sx),
                       __uint_as_float(__float_as_uint(p.y) + sy));
}

__global__ __launch_bounds__(128) void rbf_hist_kernel(
    const float* __restrict__ x,
    const float* __restrict__ centers,
    const float* __restrict__ widths,
    float* __restrict__ out)
{
    __shared__ float2 s_nc[COUT * CIN];   // (-c,-c)
    __shared__ float2 s_k[COUT * CIN];    // (k,k)

    int tid = threadIdx.x;
    if (tid < COUT * CIN) {
        float c = centers[tid];
        float w = widths[tid];
        float k = -1.44269504088896340736f / (2.0f * w * w); // exp(-d^2/2w^2)=exp2(k d^2)
        s_nc[tid] = make_float2(-c, -c);
        s_k[tid]  = make_float2(k, k);
    }
    __syncthreads();

    PolyC K;
    K.MAGIC = make_float2(12582912.0f, 12582912.0f);  // 2^23 + 2^22
    K.NEG1  = make_float2(-1.0f, -1.0f);
    K.ONE   = make_float2(1.0f, 1.0f);
    K.C1 = make_float2(0.6931471805599453f, 0.6931471805599453f);
    K.C2 = make_float2(0.2402265069591007f, 0.2402265069591007f);
    K.C3 = make_float2(0.0555041086648216f, 0.0555041086648216f);
    K.C4 = make_float2(0.0096181291076285f, 0.0096181291076285f);
    K.C5 = make_float2(0.0013333558146429f, 0.0013333558146429f);

    int idx = blockIdx.x * blockDim.x + tid;
    int b   = idx >> 14;
    int p4  = idx & (GROUPS_PER_IMG - 1);
    int xbase = b * CIN * HW + p4 * 4;
    int obase = b * COUT * HW + p4 * 4;

    float2 xa[CIN], xb[CIN];
    #pragma unroll
    for (int j = 0; j < CIN; j++) {
        float4 v = *reinterpret_cast<const float4*>(x + xbase + j * HW);
        xa[j] = make_float2(v.x, v.y);
        xb[j] = make_float2(v.z, v.w);
    }

    #pragma unroll 4
    for (int o = 0; o < COUT; o++) {
        float2 accA = make_float2(0.f, 0.f);
        float2 accB = make_float2(0.f, 0.f);
        bool poly = ((o & 3) == 0);   // 4 of 16 outputs: FMA-pipe exp2
        #pragma unroll
        for (int j = 0; j < CIN; j++) {
            float2 nc = s_nc[o * CIN + j];
            float2 k  = s_k[o * CIN + j];
            float2 dA = add2(xa[j], nc);
            float2 dB = add2(xb[j], nc);
            float2 gA = mul2(mul2(dA, k), dA);
            float2 gB = mul2(mul2(dB, k), dB);
            if (poly) {
                accA = add2(accA, exp2_fma(gA, K));
                accB = add2(accB, exp2_fma(gB, K));
            } else {
                accA = add2(accA, make_float2(ex2(gA.x), ex2(gA.y)));
                accB = add2(accB, make_float2(ex2(gB.x), ex2(gB.y)));
            }
        }
        float4 r = make_float4(accA.x, accA.y, accB.x, accB.y);
        *reinterpret_cast<float4*>(out + obase + o * HW) = r;
    }
}

extern "C" void kernel_launch(void* const* d_in, const int* in_sizes, int n_in,
                              void* d_out, int out_size)
{
    const float* x       = (const float*)d_in[0];
    const float* centers = (const float*)d_in[1];
    const float* widths  = (const float*)d_in[2];
    float* out           = (float*)d_out;

    const int threads = 128;
    const int groups  = NPIX / 4;
    const int blocks  = groups / threads;   // 1024
    rbf_hist_kernel<<<blocks, threads>>>(x, centers, widths, out);
}